// round 16
// baseline (speedup 1.0000x reference)
#include <cuda_runtime.h>
#include <cuda_fp16.h>

#define NV 5
#define NB 2
#define NC 32
#define NH 256
#define NW 320
#define HW (NH*NW)
#define CN 4

__device__ float g_proj[NB*(NV-1)*12];
// fp16-packed source views: [img8 = (v-1)*NB+b][c8][pixel], 8 channels per uint4
__device__ uint4 g_feath[(size_t)(NV-1)*NB*(NC/8)*HW];

__device__ __forceinline__ void setup_proj_body(const float* __restrict__ pm, int t) {
    int b  = t / (NV-1);
    int vi = t % (NV-1) + 1;

    double M0[3][3], m0[3], Mi[3][3], mi[3];
    for (int which = 0; which < 2; which++) {
        int v = (which == 0) ? 0 : vi;
        const float* E = pm + ((size_t)(b*NV + v)*2 + 0)*16;
        const float* K = pm + ((size_t)(b*NV + v)*2 + 1)*16;
        double (*M)[3] = (which == 0) ? M0 : Mi;
        double *m      = (which == 0) ? m0 : mi;
        for (int r = 0; r < 3; r++) {
            for (int c = 0; c < 3; c++) {
                double s = 0;
                for (int k = 0; k < 3; k++) s += (double)K[r*4+k] * (double)E[k*4+c];
                M[r][c] = s;
            }
            double s = 0;
            for (int k = 0; k < 3; k++) s += (double)K[r*4+k] * (double)E[k*4+3];
            m[r] = s;
        }
    }
    double a00=M0[0][0],a01=M0[0][1],a02=M0[0][2];
    double a10=M0[1][0],a11=M0[1][1],a12=M0[1][2];
    double a20=M0[2][0],a21=M0[2][1],a22=M0[2][2];
    double det = a00*(a11*a22-a12*a21) - a01*(a10*a22-a12*a20) + a02*(a10*a21-a11*a20);
    double id = 1.0/det;
    double I[3][3];
    I[0][0]=(a11*a22-a12*a21)*id; I[0][1]=(a02*a21-a01*a22)*id; I[0][2]=(a01*a12-a02*a11)*id;
    I[1][0]=(a12*a20-a10*a22)*id; I[1][1]=(a00*a22-a02*a20)*id; I[1][2]=(a02*a10-a00*a12)*id;
    I[2][0]=(a10*a21-a11*a20)*id; I[2][1]=(a01*a20-a00*a21)*id; I[2][2]=(a00*a11-a01*a10)*id;

    double R[3][3], tv[3];
    for (int r = 0; r < 3; r++)
        for (int c = 0; c < 3; c++) {
            double s = 0;
            for (int k = 0; k < 3; k++) s += Mi[r][k]*I[k][c];
            R[r][c] = s;
        }
    for (int r = 0; r < 3; r++) {
        double s = 0;
        for (int k = 0; k < 3; k++) s += R[r][k]*m0[k];
        tv[r] = mi[r] - s;
    }
    float* o = g_proj + t*12;
    o[0]=(float)R[0][0]; o[1]=(float)R[0][1]; o[2]=(float)R[0][2];
    o[3]=(float)R[1][0]; o[4]=(float)R[1][1]; o[5]=(float)R[1][2];
    o[6]=(float)R[2][0]; o[7]=(float)R[2][1]; o[8]=(float)R[2][2];
    o[9]=(float)tv[0]; o[10]=(float)tv[1]; o[11]=(float)tv[2];
}

// float CHW (views 1..4) -> half8-packed planes (uint4), 1 pixel per thread.
// Block (0,0) additionally computes the projection matrices (merged setup node).
__global__ void __launch_bounds__(256)
convert_kernel(const float* __restrict__ feat, const float* __restrict__ pm) {
    if (blockIdx.x == 0 && blockIdx.y == 0 && threadIdx.x < NB*(NV-1))
        setup_proj_body(pm, threadIdx.x);

    int plane = blockIdx.y;            // 0..31 : img8*4 + c8
    int img8  = plane >> 2;
    int c8    = plane & 3;
    int p = blockIdx.x * 256 + threadIdx.x;
    const float* src = feat + ((size_t)(NB + img8)*NC + c8*8)*HW + p;
    __half2 h0 = __floats2half2_rn(src[0],    src[HW]);
    __half2 h1 = __floats2half2_rn(src[2*HW], src[3*HW]);
    __half2 h2 = __floats2half2_rn(src[4*HW], src[5*HW]);
    __half2 h3 = __floats2half2_rn(src[6*HW], src[7*HW]);
    uint4 o;
    o.x = *reinterpret_cast<unsigned*>(&h0);
    o.y = *reinterpret_cast<unsigned*>(&h1);
    o.z = *reinterpret_cast<unsigned*>(&h2);
    o.w = *reinterpret_cast<unsigned*>(&h3);
    g_feath[(size_t)plane*HW + p] = o;
}

__device__ __forceinline__ float2 h2f(unsigned u) {
    __half2 h = *reinterpret_cast<__half2*>(&u);
    return __half22float2(h);
}

__device__ __forceinline__ float dot8(const uint4 a, const float* __restrict__ r) {
    float2 e0 = h2f(a.x), e1 = h2f(a.y), e2 = h2f(a.z), e3 = h2f(a.w);
    float s = r[0]*e0.x;
    s = fmaf(r[1], e0.y, s);
    s = fmaf(r[2], e1.x, s);
    s = fmaf(r[3], e1.y, s);
    s = fmaf(r[4], e2.x, s);
    s = fmaf(r[5], e2.y, s);
    s = fmaf(r[6], e3.x, s);
    s = fmaf(r[7], e3.y, s);
    return s;
}

__global__ void __launch_bounds__(256, 3)
getcost_kernel(const float* __restrict__ feat,
               const float* __restrict__ dvals,
               const float* __restrict__ dint,
               const float* __restrict__ vwts,
               float* __restrict__ out)
{
    __shared__ float sproj[NB*(NV-1)*12];
    __shared__ float tile[8][CN][32];    // [warp][d][lane] staging for float4 stores
    for (int i = threadIdx.x; i < NB*(NV-1)*12; i += 256) sproj[i] = g_proj[i];
    __syncthreads();

    int pix = blockIdx.x * 256 + threadIdx.x;
    int b = pix / HW;
    int p = pix - b*HW;
    int yy = p / NW;
    int xx = p - yy*NW;
    float fx = (float)xx, fy = (float)yy;

    float invd = __frcp_rn(dvals[pix]);
    float itv  = dint[pix];
    float low  = invd - (CN*0.5f)*itv;
    float step = itv * ((float)CN/(CN-1));

    float z[CN];
#pragma unroll
    for (int d = 0; d < CN; d++) z[d] = __frcp_rn(low + (float)d*step);

    float vwr[NV-1];
#pragma unroll
    for (int j = 0; j < NV-1; j++)
        vwr[j] = __ldg(vwts + ((size_t)(b*(NV-1)+j))*HW + p);
    float wsum = 1e-5f + vwr[0] + vwr[1] + vwr[2] + vwr[3];

    // fp32 reference features (coalesced)
    float ref[NC];
    const float* rbase = feat + (size_t)b*NC*HW + p;
#pragma unroll
    for (int c = 0; c < NC; c++) ref[c] = __ldg(rbase + (size_t)c*HW);

    float vol[CN] = {0.f,0.f,0.f,0.f};
    const float* PRb = sproj + b*(NV-1)*12;

#pragma unroll
    for (int vi = 1; vi < NV; vi++) {
        const float* PR = PRb + (vi-1)*12;
        float u0 = fmaf(PR[0], fx, fmaf(PR[1], fy, PR[2]));
        float u1 = fmaf(PR[3], fx, fmaf(PR[4], fy, PR[5]));
        float u2 = fmaf(PR[6], fx, fmaf(PR[7], fy, PR[8]));
        float t0 = PR[9], t1 = PR[10], t2 = PR[11];
        float vw = vwr[vi-1];
        const uint4* fp = g_feath + (size_t)((vi-1)*NB + b)*(NC/8)*HW;

#pragma unroll
        for (int d = 0; d < CN; d++) {
            float zz = z[d];
            float pz = fmaf(u2, zz, t2);
            float rz = __frcp_rn(pz);
            float gx = fmaf(u0, zz, t0) * rz;
            float gy = fmaf(u1, zz, t1) * rz;

            float x0f = floorf(gx), y0f = floorf(gy);
            float wx = gx - x0f, wy = gy - y0f;

            bool vx0 = (x0f >=  0.f) && (x0f <= (float)(NW-1));
            bool vx1 = (x0f >= -1.f) && (x0f <= (float)(NW-2));
            bool vy0 = (y0f >=  0.f) && (y0f <= (float)(NH-1));
            bool vy1 = (y0f >= -1.f) && (y0f <= (float)(NH-2));

            int x0i = (int)fminf(fmaxf(x0f,       0.f), (float)(NW-1));
            int x1i = (int)fminf(fmaxf(x0f + 1.f, 0.f), (float)(NW-1));
            int y0i = (int)fminf(fmaxf(y0f,       0.f), (float)(NH-1));
            int y1i = (int)fminf(fmaxf(y0f + 1.f, 0.f), (float)(NH-1));

            int i00 = y0i*NW + x0i;
            int i01 = y0i*NW + x1i;
            int i10 = y1i*NW + x0i;
            int i11 = y1i*NW + x1i;

            float S00 = 0.f, S01 = 0.f, S10 = 0.f, S11 = 0.f;
#pragma unroll
            for (int c8 = 0; c8 < NC/8; c8++) {
                const uint4* pl = fp + (size_t)c8*HW;
                uint4 a00 = __ldg(pl + i00);
                uint4 a01 = __ldg(pl + i01);
                uint4 a10 = __ldg(pl + i10);
                uint4 a11 = __ldg(pl + i11);
                const float* r = ref + c8*8;
                S00 += dot8(a00, r);
                S01 += dot8(a01, r);
                S10 += dot8(a10, r);
                S11 += dot8(a11, r);
            }

            float iwx = 1.f - wx, iwy = 1.f - wy;
            float w00 = (vx0 && vy0) ? iwx*iwy : 0.f;
            float w01 = (vx1 && vy0) ? wx*iwy  : 0.f;
            float w10 = (vx0 && vy1) ? iwx*wy  : 0.f;
            float w11 = (vx1 && vy1) ? wx*wy   : 0.f;

            float val = fmaf(w00,S00, fmaf(w01,S01, fmaf(w10,S10, w11*S11)));
            vol[d] = fmaf(vw, val, vol[d]);
        }
    }

    // ---- staged float4 store epilogue ----
    int w    = threadIdx.x >> 5;
    int lane = threadIdx.x & 31;
    float scale = __frcp_rn((float)NC * wsum);
#pragma unroll
    for (int d = 0; d < CN; d++)
        tile[w][d][lane] = vol[d] * scale;
    __syncwarp();

    // lane -> (g = lane&7 pixel-group, d = lane>>3); loop over c
    int g = lane & 7;
    int d = lane >> 3;
    int pix0 = blockIdx.x * 256 + w * 32;     // warp's first pixel
    int wb   = pix0 / HW;
    int wp0  = pix0 - wb*HW;
    float4 v4 = *reinterpret_cast<const float4*>(&tile[w][d][g*4]);
    float* ob = out + ((size_t)(wb*NC)*CN + d)*HW + wp0 + g*4;
#pragma unroll 8
    for (int c = 0; c < NC; c++)
        *reinterpret_cast<float4*>(ob + (size_t)c*CN*HW) = v4;
}

extern "C" void kernel_launch(void* const* d_in, const int* in_sizes, int n_in,
                              void* d_out, int out_size) {
    const float *feat = nullptr, *projm = nullptr, *vw = nullptr;
    const float *dv = nullptr, *di = nullptr;
    const int sz_feat = NV*NB*NC*HW;
    const int sz_proj = NB*NV*2*16;
    const int sz_vw   = NB*(NV-1)*HW;
    const int sz_map  = NB*HW;
    for (int i = 0; i < n_in; i++) {
        int s = in_sizes[i];
        if (s == sz_feat)            feat  = (const float*)d_in[i];
        else if (s == sz_proj)       projm = (const float*)d_in[i];
        else if (s == sz_vw)         vw    = (const float*)d_in[i];
        else if (s == sz_map) {
            if (!dv) dv = (const float*)d_in[i];
            else if (!di) di = (const float*)d_in[i];
        }
    }
    float* out = (float*)d_out;

    convert_kernel<<<dim3(HW/256, (NV-1)*NB*(NC/8)), 256>>>(feat, projm);
    getcost_kernel<<<(NB*HW)/256, 256>>>(feat, dv, di, vw, out);
}

// round 17
// speedup vs baseline: 1.1517x; 1.1517x over previous
#include <cuda_runtime.h>
#include <cuda_fp16.h>

#define NV 5
#define NB 2
#define NC 32
#define NH 256
#define NW 320
#define HW (NH*NW)
#define CN 4

__device__ float g_proj[NB*(NV-1)*12];
// fp16-packed source views: [img8 = (v-1)*NB+b][c8][pixel], 8 channels per uint4
__device__ uint4 g_feath[(size_t)(NV-1)*NB*(NC/8)*HW];

// float32 throughout — matches the reference (jnp float32 linalg).
__device__ __forceinline__ void setup_proj_body(const float* __restrict__ pm, int t) {
    int b  = t / (NV-1);
    int vi = t % (NV-1) + 1;

    float M0[3][3], m0[3], Mi[3][3], mi[3];
    for (int which = 0; which < 2; which++) {
        int v = (which == 0) ? 0 : vi;
        const float* E = pm + ((size_t)(b*NV + v)*2 + 0)*16;
        const float* K = pm + ((size_t)(b*NV + v)*2 + 1)*16;
        float (*M)[3] = (which == 0) ? M0 : Mi;
        float *m      = (which == 0) ? m0 : mi;
        for (int r = 0; r < 3; r++) {
            for (int c = 0; c < 3; c++) {
                float s = 0.f;
                for (int k = 0; k < 3; k++) s += K[r*4+k] * E[k*4+c];
                M[r][c] = s;
            }
            float s = 0.f;
            for (int k = 0; k < 3; k++) s += K[r*4+k] * E[k*4+3];
            m[r] = s;
        }
    }
    float a00=M0[0][0],a01=M0[0][1],a02=M0[0][2];
    float a10=M0[1][0],a11=M0[1][1],a12=M0[1][2];
    float a20=M0[2][0],a21=M0[2][1],a22=M0[2][2];
    float det = a00*(a11*a22-a12*a21) - a01*(a10*a22-a12*a20) + a02*(a10*a21-a11*a20);
    float id = 1.0f/det;
    float I[3][3];
    I[0][0]=(a11*a22-a12*a21)*id; I[0][1]=(a02*a21-a01*a22)*id; I[0][2]=(a01*a12-a02*a11)*id;
    I[1][0]=(a12*a20-a10*a22)*id; I[1][1]=(a00*a22-a02*a20)*id; I[1][2]=(a02*a10-a00*a12)*id;
    I[2][0]=(a10*a21-a11*a20)*id; I[2][1]=(a01*a20-a00*a21)*id; I[2][2]=(a00*a11-a01*a10)*id;

    float R[3][3], tv[3];
    for (int r = 0; r < 3; r++)
        for (int c = 0; c < 3; c++) {
            float s = 0.f;
            for (int k = 0; k < 3; k++) s += Mi[r][k]*I[k][c];
            R[r][c] = s;
        }
    for (int r = 0; r < 3; r++) {
        float s = 0.f;
        for (int k = 0; k < 3; k++) s += R[r][k]*m0[k];
        tv[r] = mi[r] - s;
    }
    float* o = g_proj + t*12;
    o[0]=R[0][0]; o[1]=R[0][1]; o[2]=R[0][2];
    o[3]=R[1][0]; o[4]=R[1][1]; o[5]=R[1][2];
    o[6]=R[2][0]; o[7]=R[2][1]; o[8]=R[2][2];
    o[9]=tv[0]; o[10]=tv[1]; o[11]=tv[2];
}

// float CHW (views 1..4) -> half8-packed planes (uint4), 1 pixel per thread.
// Block (0,0) additionally computes the projection matrices (merged setup node).
__global__ void __launch_bounds__(256)
convert_kernel(const float* __restrict__ feat, const float* __restrict__ pm) {
    if (blockIdx.x == 0 && blockIdx.y == 0 && threadIdx.x < NB*(NV-1))
        setup_proj_body(pm, threadIdx.x);

    int plane = blockIdx.y;            // 0..31 : img8*4 + c8
    int img8  = plane >> 2;
    int c8    = plane & 3;
    int p = blockIdx.x * 256 + threadIdx.x;
    const float* src = feat + ((size_t)(NB + img8)*NC + c8*8)*HW + p;
    __half2 h0 = __floats2half2_rn(src[0],    src[HW]);
    __half2 h1 = __floats2half2_rn(src[2*HW], src[3*HW]);
    __half2 h2 = __floats2half2_rn(src[4*HW], src[5*HW]);
    __half2 h3 = __floats2half2_rn(src[6*HW], src[7*HW]);
    uint4 o;
    o.x = *reinterpret_cast<unsigned*>(&h0);
    o.y = *reinterpret_cast<unsigned*>(&h1);
    o.z = *reinterpret_cast<unsigned*>(&h2);
    o.w = *reinterpret_cast<unsigned*>(&h3);
    g_feath[(size_t)plane*HW + p] = o;
}

__device__ __forceinline__ float2 h2f(unsigned u) {
    __half2 h = *reinterpret_cast<__half2*>(&u);
    return __half22float2(h);
}

__device__ __forceinline__ float dot8(const uint4 a, const float* __restrict__ r) {
    float2 e0 = h2f(a.x), e1 = h2f(a.y), e2 = h2f(a.z), e3 = h2f(a.w);
    float s = r[0]*e0.x;
    s = fmaf(r[1], e0.y, s);
    s = fmaf(r[2], e1.x, s);
    s = fmaf(r[3], e1.y, s);
    s = fmaf(r[4], e2.x, s);
    s = fmaf(r[5], e2.y, s);
    s = fmaf(r[6], e3.x, s);
    s = fmaf(r[7], e3.y, s);
    return s;
}

__global__ void __launch_bounds__(256, 3)
getcost_kernel(const float* __restrict__ feat,
               const float* __restrict__ dvals,
               const float* __restrict__ dint,
               const float* __restrict__ vwts,
               float* __restrict__ out)
{
    __shared__ float sproj[NB*(NV-1)*12];
    __shared__ float tile[8][CN][32];    // [warp][d][lane] staging for float4 stores
    for (int i = threadIdx.x; i < NB*(NV-1)*12; i += 256) sproj[i] = g_proj[i];
    __syncthreads();

    int pix = blockIdx.x * 256 + threadIdx.x;
    int b = pix / HW;
    int p = pix - b*HW;
    int yy = p / NW;
    int xx = p - yy*NW;
    float fx = (float)xx, fy = (float)yy;

    float invd = __frcp_rn(dvals[pix]);
    float itv  = dint[pix];
    float low  = invd - (CN*0.5f)*itv;
    float step = itv * ((float)CN/(CN-1));

    float z[CN];
#pragma unroll
    for (int d = 0; d < CN; d++) z[d] = __frcp_rn(low + (float)d*step);

    float vwr[NV-1];
#pragma unroll
    for (int j = 0; j < NV-1; j++)
        vwr[j] = __ldg(vwts + ((size_t)(b*(NV-1)+j))*HW + p);
    float wsum = 1e-5f + vwr[0] + vwr[1] + vwr[2] + vwr[3];

    // fp32 reference features (coalesced)
    float ref[NC];
    const float* rbase = feat + (size_t)b*NC*HW + p;
#pragma unroll
    for (int c = 0; c < NC; c++) ref[c] = __ldg(rbase + (size_t)c*HW);

    float vol[CN] = {0.f,0.f,0.f,0.f};
    const float* PRb = sproj + b*(NV-1)*12;

#pragma unroll
    for (int vi = 1; vi < NV; vi++) {
        const float* PR = PRb + (vi-1)*12;
        float u0 = fmaf(PR[0], fx, fmaf(PR[1], fy, PR[2]));
        float u1 = fmaf(PR[3], fx, fmaf(PR[4], fy, PR[5]));
        float u2 = fmaf(PR[6], fx, fmaf(PR[7], fy, PR[8]));
        float t0 = PR[9], t1 = PR[10], t2 = PR[11];
        float vw = vwr[vi-1];
        const uint4* fp = g_feath + (size_t)((vi-1)*NB + b)*(NC/8)*HW;

#pragma unroll
        for (int d = 0; d < CN; d++) {
            float zz = z[d];
            float pz = fmaf(u2, zz, t2);
            float rz = __frcp_rn(pz);
            float gx = fmaf(u0, zz, t0) * rz;
            float gy = fmaf(u1, zz, t1) * rz;

            float x0f = floorf(gx), y0f = floorf(gy);
            float wx = gx - x0f, wy = gy - y0f;

            bool vx0 = (x0f >=  0.f) && (x0f <= (float)(NW-1));
            bool vx1 = (x0f >= -1.f) && (x0f <= (float)(NW-2));
            bool vy0 = (y0f >=  0.f) && (y0f <= (float)(NH-1));
            bool vy1 = (y0f >= -1.f) && (y0f <= (float)(NH-2));

            int x0i = (int)fminf(fmaxf(x0f,       0.f), (float)(NW-1));
            int x1i = (int)fminf(fmaxf(x0f + 1.f, 0.f), (float)(NW-1));
            int y0i = (int)fminf(fmaxf(y0f,       0.f), (float)(NH-1));
            int y1i = (int)fminf(fmaxf(y0f + 1.f, 0.f), (float)(NH-1));

            int i00 = y0i*NW + x0i;
            int i01 = y0i*NW + x1i;
            int i10 = y1i*NW + x0i;
            int i11 = y1i*NW + x1i;

            float S00 = 0.f, S01 = 0.f, S10 = 0.f, S11 = 0.f;
#pragma unroll
            for (int c8 = 0; c8 < NC/8; c8++) {
                const uint4* pl = fp + (size_t)c8*HW;
                uint4 a00 = __ldg(pl + i00);
                uint4 a01 = __ldg(pl + i01);
                uint4 a10 = __ldg(pl + i10);
                uint4 a11 = __ldg(pl + i11);
                const float* r = ref + c8*8;
                S00 += dot8(a00, r);
                S01 += dot8(a01, r);
                S10 += dot8(a10, r);
                S11 += dot8(a11, r);
            }

            float iwx = 1.f - wx, iwy = 1.f - wy;
            float w00 = (vx0 && vy0) ? iwx*iwy : 0.f;
            float w01 = (vx1 && vy0) ? wx*iwy  : 0.f;
            float w10 = (vx0 && vy1) ? iwx*wy  : 0.f;
            float w11 = (vx1 && vy1) ? wx*wy   : 0.f;

            float val = fmaf(w00,S00, fmaf(w01,S01, fmaf(w10,S10, w11*S11)));
            vol[d] = fmaf(vw, val, vol[d]);
        }
    }

    // ---- staged float4 store epilogue ----
    int w    = threadIdx.x >> 5;
    int lane = threadIdx.x & 31;
    float scale = __frcp_rn((float)NC * wsum);
#pragma unroll
    for (int d = 0; d < CN; d++)
        tile[w][d][lane] = vol[d] * scale;
    __syncwarp();

    // lane -> (g = lane&7 pixel-group, d = lane>>3); loop over c
    int g = lane & 7;
    int d = lane >> 3;
    int pix0 = blockIdx.x * 256 + w * 32;     // warp's first pixel
    int wb   = pix0 / HW;
    int wp0  = pix0 - wb*HW;
    float4 v4 = *reinterpret_cast<const float4*>(&tile[w][d][g*4]);
    float* ob = out + ((size_t)(wb*NC)*CN + d)*HW + wp0 + g*4;
#pragma unroll 8
    for (int c = 0; c < NC; c++)
        *reinterpret_cast<float4*>(ob + (size_t)c*CN*HW) = v4;
}

extern "C" void kernel_launch(void* const* d_in, const int* in_sizes, int n_in,
                              void* d_out, int out_size) {
    const float *feat = nullptr, *projm = nullptr, *vw = nullptr;
    const float *dv = nullptr, *di = nullptr;
    const int sz_feat = NV*NB*NC*HW;
    const int sz_proj = NB*NV*2*16;
    const int sz_vw   = NB*(NV-1)*HW;
    const int sz_map  = NB*HW;
    for (int i = 0; i < n_in; i++) {
        int s = in_sizes[i];
        if (s == sz_feat)            feat  = (const float*)d_in[i];
        else if (s == sz_proj)       projm = (const float*)d_in[i];
        else if (s == sz_vw)         vw    = (const float*)d_in[i];
        else if (s == sz_map) {
            if (!dv) dv = (const float*)d_in[i];
            else if (!di) di = (const float*)d_in[i];
        }
    }
    float* out = (float*)d_out;

    convert_kernel<<<dim3(HW/256, (NV-1)*NB*(NC/8)), 256>>>(feat, projm);
    getcost_kernel<<<(NB*HW)/256, 256>>>(feat, dv, di, vw, out);
}